// round 7
// baseline (speedup 1.0000x reference)
#include <cuda_runtime.h>
#include <stdint.h>

#define HW      49
#define KP      56        // q padded (7 k-steps of 8)
#define MPAD    64        // p padded
#define CT      64        // c per CTA
#define CCOLS   512
#define THREADS 256
#define RA      68        // A row stride (floats), ==4 mod 32 -> conflict-free frags
#define RB      72        // B row stride (floats), ==8 mod 32 -> conflict-free frags

// smem: Ah[64*68] | Al[64*68] | Bh[56*72] | Bl[56*72] ; Y reuses Bh region
#define OFF_AL  (MPAD*RA)             // uint32 index
#define OFF_B   (2*MPAD*RA*4)         // byte offset 34816
#define SMEM_BYTES (OFF_B + 2*KP*RB*4)  // 67072

__device__ __forceinline__ uint32_t f2tf32(float v) {
    uint32_t r;
    asm("cvt.rna.tf32.f32 %0, %1;" : "=r"(r) : "f"(v));
    return r;
}

__device__ __forceinline__ void mma8(float* d, uint32_t a0, uint32_t a1, uint32_t a2, uint32_t a3,
                                     uint32_t b0, uint32_t b1) {
    asm volatile(
        "mma.sync.aligned.m16n8k8.row.col.f32.tf32.tf32.f32 "
        "{%0,%1,%2,%3}, {%4,%5,%6,%7}, {%8,%9}, {%0,%1,%2,%3};"
        : "+f"(d[0]), "+f"(d[1]), "+f"(d[2]), "+f"(d[3])
        : "r"(a0), "r"(a1), "r"(a2), "r"(a3), "r"(b0), "r"(b1));
}

__global__ __launch_bounds__(THREADS, 3)
void bmm_tf32_kernel(const float* __restrict__ x,
                     const float* __restrict__ attn,
                     const float* __restrict__ Dm,
                     const float* __restrict__ alpha,
                     float* __restrict__ out)
{
    extern __shared__ __align__(16) char sm[];
    uint32_t* Ah = (uint32_t*)sm;
    uint32_t* Al = Ah + OFF_AL;
    uint32_t* Bh = (uint32_t*)(sm + OFF_B);
    uint32_t* Bl = Bh + KP * RB;
    float*    Ysh = (float*)(sm + OFF_B);        // reuse Bh region post-MMA (12544 <= 16128)

    const int n   = blockIdx.y;
    const int c0  = blockIdx.x * CT;
    const int tid = threadIdx.x;
    const int wid = tid >> 5;
    const int lid = tid & 31;
    const int g   = lid >> 2;     // groupID (row within frag)
    const int t   = lid & 3;      // thread-in-group (col within frag)

    // ---- zero all operand smem (covers the k/p padding) ----
    {
        float4 z = make_float4(0.f, 0.f, 0.f, 0.f);
        float4* zp = (float4*)sm;
        for (int i = tid; i < SMEM_BYTES / 16; i += THREADS) zp[i] = z;
    }
    __syncthreads();

    // ---- stage A = attn[n] (49x49) as tf32 hi/lo, row-major [m][k] ----
    const float* An = attn + (size_t)n * HW * HW;
    for (int i = tid; i < HW * HW; i += THREADS) {
        int p = i / HW, q = i - p * HW;
        float v = An[i];
        uint32_t h = f2tf32(v);
        float lf = v - __uint_as_float(h);
        Ah[p * RA + q] = h;
        Al[p * RA + q] = f2tf32(lf);
    }

    // ---- stage B = D[n][q][c0..c0+63] as tf32 hi/lo, [k][n] (native order) ----
    const float* Dn = Dm + (size_t)n * HW * CCOLS + c0;
    for (int i = tid; i < HW * (CT / 4); i += THREADS) {
        int q = i >> 4, j = i & 15;                  // c = 4j
        float4 v = *(const float4*)(Dn + (size_t)q * CCOLS + 4 * j);
        uint4 hh, ll;
        hh.x = f2tf32(v.x); hh.y = f2tf32(v.y); hh.z = f2tf32(v.z); hh.w = f2tf32(v.w);
        ll.x = f2tf32(v.x - __uint_as_float(hh.x));
        ll.y = f2tf32(v.y - __uint_as_float(hh.y));
        ll.z = f2tf32(v.z - __uint_as_float(hh.z));
        ll.w = f2tf32(v.w - __uint_as_float(hh.w));
        *(uint4*)(Bh + q * RB + 4 * j) = hh;
        *(uint4*)(Bl + q * RB + 4 * j) = ll;
    }
    __syncthreads();

    // ---- mainloop: warp = (m-tile = wid&3, n-half = wid>>2); 4 n-tiles each ----
    const int mb = (wid & 3) * 16;
    const int nb = (wid >> 2) * 32;

    float acc[4][4];
#pragma unroll
    for (int nt = 0; nt < 4; ++nt)
#pragma unroll
        for (int d = 0; d < 4; ++d) acc[nt][d] = 0.f;

    const uint32_t* ah = Ah + (mb + g) * RA + t;
    const uint32_t* al = Al + (mb + g) * RA + t;
    const uint32_t* bh = Bh + t * RB + nb + g;
    const uint32_t* bl = Bl + t * RB + nb + g;

#pragma unroll
    for (int k0 = 0; k0 < 7; ++k0) {
        const int ka = k0 * 8;
        uint32_t ah0 = ah[ka],          ah1 = ah[8 * RA + ka];
        uint32_t ah2 = ah[ka + 4],      ah3 = ah[8 * RA + ka + 4];
        uint32_t al0 = al[ka],          al1 = al[8 * RA + ka];
        uint32_t al2 = al[ka + 4],      al3 = al[8 * RA + ka + 4];
#pragma unroll
        for (int nt = 0; nt < 4; ++nt) {
            uint32_t bh0 = bh[ka * RB + nt * 8];
            uint32_t bh1 = bh[(ka + 4) * RB + nt * 8];
            uint32_t bl0 = bl[ka * RB + nt * 8];
            uint32_t bl1 = bl[(ka + 4) * RB + nt * 8];
            mma8(acc[nt], ah0, ah1, ah2, ah3, bh0, bh1);   // Ah*Bh
            mma8(acc[nt], al0, al1, al2, al3, bh0, bh1);   // Al*Bh
            mma8(acc[nt], ah0, ah1, ah2, ah3, bl0, bl1);   // Ah*Bl
        }
    }
    __syncthreads();     // all B reads done — safe to reuse region as Y

    // ---- scatter Y[c][p] into smem for contiguous gmem writes ----
    {
        const int p0 = mb + g, p1 = p0 + 8;
#pragma unroll
        for (int nt = 0; nt < 4; ++nt) {
            const int c = nb + nt * 8 + 2 * t;
            if (p0 < HW) {
                Ysh[c * HW + p0]       = acc[nt][0];
                Ysh[(c + 1) * HW + p0] = acc[nt][1];
            }
            if (p1 < HW) {
                Ysh[c * HW + p1]       = acc[nt][2];
                Ysh[(c + 1) * HW + p1] = acc[nt][3];
            }
        }
    }
    __syncthreads();

    // ---- residual epilogue: out[n, c0:c0+64, :] contiguous (3136 floats) ----
    const float  al_  = alpha[0];
    const size_t base = (size_t)n * CCOLS * HW + (size_t)c0 * HW;
    const float4* x4  = (const float4*)(x + base);
    const float4* y4  = (const float4*)Ysh;
    float4*       o4  = (float4*)(out + base);
    for (int i = tid; i < (CT * HW) / 4; i += THREADS) {   // 784
        float4 xv = x4[i], yv = y4[i], ov;
        ov.x = fmaf(al_, yv.x, xv.x);
        ov.y = fmaf(al_, yv.y, xv.y);
        ov.z = fmaf(al_, yv.z, xv.z);
        ov.w = fmaf(al_, yv.w, xv.w);
        o4[i] = ov;
    }
}

extern "C" void kernel_launch(void* const* d_in, const int* in_sizes, int n_in,
                              void* d_out, int out_size)
{
    const float* x     = (const float*)d_in[0];
    const float* attn  = (const float*)d_in[1];
    const float* Dm    = (const float*)d_in[2];
    const float* alpha = (const float*)d_in[3];
    float*       out   = (float*)d_out;

    cudaFuncSetAttribute(bmm_tf32_kernel, cudaFuncAttributeMaxDynamicSharedMemorySize, SMEM_BYTES);

    const int N = in_sizes[1] / (HW * HW);   // 2048
    dim3 grid(CCOLS / CT, N);                // (8, 2048)
    bmm_tf32_kernel<<<grid, THREADS, SMEM_BYTES>>>(x, attn, Dm, alpha, out);
}

// round 8
// speedup vs baseline: 1.4082x; 1.4082x over previous
#include <cuda_runtime.h>
#include <stdint.h>

#define HW      49
#define KP      56        // q padded (7 k-steps of 8)
#define MPAD    64        // p padded
#define CT      64        // c per CTA
#define CCOLS   512
#define THREADS 256
#define RA      68        // A row stride (floats), ==4 mod 32 -> conflict-free frags
#define RB      72        // B row stride (floats), ==8 mod 32 -> conflict-free frags

// smem: Afp[64*68] fp32 (17408 B) | Bfp[56*72] fp32 (16128 B); Y reuses B region
#define OFF_B      (MPAD*RA)                 // float index of B
#define SMEM_BYTES ((MPAD*RA + KP*RB) * 4)   // 33536

__device__ __forceinline__ uint32_t f2tf32(float v) {
    uint32_t r;
    asm("cvt.rna.tf32.f32 %0, %1;" : "=r"(r) : "f"(v));
    return r;
}

// in-register hi/lo split (exact: lo = v - hi in fp32)
__device__ __forceinline__ void split(float v, uint32_t& h, uint32_t& l) {
    h = f2tf32(v);
    l = f2tf32(v - __uint_as_float(h));
}

__device__ __forceinline__ void mma8(float* d, uint32_t a0, uint32_t a1, uint32_t a2, uint32_t a3,
                                     uint32_t b0, uint32_t b1) {
    asm volatile(
        "mma.sync.aligned.m16n8k8.row.col.f32.tf32.tf32.f32 "
        "{%0,%1,%2,%3}, {%4,%5,%6,%7}, {%8,%9}, {%0,%1,%2,%3};"
        : "+f"(d[0]), "+f"(d[1]), "+f"(d[2]), "+f"(d[3])
        : "r"(a0), "r"(a1), "r"(a2), "r"(a3), "r"(b0), "r"(b1));
}

__global__ __launch_bounds__(THREADS, 5)
void bmm_tf32_kernel(const float* __restrict__ x,
                     const float* __restrict__ attn,
                     const float* __restrict__ Dm,
                     const float* __restrict__ alpha,
                     float* __restrict__ out)
{
    extern __shared__ __align__(16) float sm[];
    float* Afp = sm;              // [64][68] fp32, rows>=49 / cols>=49 zero
    float* Bfp = sm + OFF_B;      // [56][72] fp32, rows>=49 zero
    float* Ysh = Bfp;             // Y[c*49+p] fp32 (12544 B) reuses B post-MMA

    const int n   = blockIdx.y;
    const int c0  = blockIdx.x * CT;
    const int tid = threadIdx.x;
    const int wid = tid >> 5;
    const int lid = tid & 31;
    const int g   = lid >> 2;     // groupID
    const int t   = lid & 3;      // thread-in-group

    // ---- stage A = attn[n] (49x49) fp32, zero-padded to 64x56 ----
    const float* An = attn + (size_t)n * HW * HW;
    for (int i = tid; i < MPAD * KP; i += THREADS) {        // 3584
        int p = i / KP, q = i - p * KP;
        Afp[p * RA + q] = (p < HW && q < HW) ? An[p * HW + q] : 0.f;
    }

    // ---- stage B = D[n][q][c0..c0+63] fp32 [k][n], rows q>=49 zero ----
    const float* Dn = Dm + (size_t)n * HW * CCOLS + c0;
    for (int i = tid; i < KP * (CT / 4); i += THREADS) {    // 896 float4
        int q = i >> 4, j = i & 15;                         // c = 4j
        float4 v = (q < HW) ? *(const float4*)(Dn + (size_t)q * CCOLS + 4 * j)
                            : make_float4(0.f, 0.f, 0.f, 0.f);
        *(float4*)(Bfp + q * RB + 4 * j) = v;
    }
    __syncthreads();

    // ---- mainloop: warp = (m-tile = wid&3, n-half = wid>>2); 4 n-tiles each ----
    const int mb = (wid & 3) * 16;
    const int nb = (wid >> 2) * 32;

    float acc[4][4];
#pragma unroll
    for (int nt = 0; nt < 4; ++nt)
#pragma unroll
        for (int d = 0; d < 4; ++d) acc[nt][d] = 0.f;

    const float* aB = Afp + (mb + g) * RA + t;
    const float* bB = Bfp + t * RB + nb + g;

#pragma unroll
    for (int k0 = 0; k0 < 7; ++k0) {
        const int ka = k0 * 8;
        uint32_t ah0, ah1, ah2, ah3, al0, al1, al2, al3;
        split(aB[ka],              ah0, al0);
        split(aB[8 * RA + ka],     ah1, al1);
        split(aB[ka + 4],          ah2, al2);
        split(aB[8 * RA + ka + 4], ah3, al3);
#pragma unroll
        for (int nt = 0; nt < 4; ++nt) {
            uint32_t bh0, bh1, bl0, bl1;
            split(bB[ka * RB + nt * 8],       bh0, bl0);
            split(bB[(ka + 4) * RB + nt * 8], bh1, bl1);
            mma8(acc[nt], ah0, ah1, ah2, ah3, bh0, bh1);   // Ah*Bh
            mma8(acc[nt], al0, al1, al2, al3, bh0, bh1);   // Al*Bh
            mma8(acc[nt], ah0, ah1, ah2, ah3, bl0, bl1);   // Ah*Bl
        }
    }
    __syncthreads();     // all B reads done — safe to reuse region as Y

    // ---- scatter Y[c][p] into smem for contiguous gmem writes ----
    {
        const int p0 = mb + g, p1 = p0 + 8;
#pragma unroll
        for (int nt = 0; nt < 4; ++nt) {
            const int c = nb + nt * 8 + 2 * t;
            if (p0 < HW) {
                Ysh[c * HW + p0]       = acc[nt][0];
                Ysh[(c + 1) * HW + p0] = acc[nt][1];
            }
            if (p1 < HW) {
                Ysh[c * HW + p1]       = acc[nt][2];
                Ysh[(c + 1) * HW + p1] = acc[nt][3];
            }
        }
    }
    __syncthreads();

    // ---- residual epilogue: out[n, c0:c0+64, :] contiguous (3136 floats) ----
    const float  al_  = alpha[0];
    const size_t base = (size_t)n * CCOLS * HW + (size_t)c0 * HW;
    const float4* x4  = (const float4*)(x + base);
    const float4* y4  = (const float4*)Ysh;
    float4*       o4  = (float4*)(out + base);
    for (int i = tid; i < (CT * HW) / 4; i += THREADS) {   // 784
        float4 xv = x4[i], yv = y4[i], ov;
        ov.x = fmaf(al_, yv.x, xv.x);
        ov.y = fmaf(al_, yv.y, xv.y);
        ov.z = fmaf(al_, yv.z, xv.z);
        ov.w = fmaf(al_, yv.w, xv.w);
        o4[i] = ov;
    }
}

extern "C" void kernel_launch(void* const* d_in, const int* in_sizes, int n_in,
                              void* d_out, int out_size)
{
    const float* x     = (const float*)d_in[0];
    const float* attn  = (const float*)d_in[1];
    const float* Dm    = (const float*)d_in[2];
    const float* alpha = (const float*)d_in[3];
    float*       out   = (float*)d_out;

    cudaFuncSetAttribute(bmm_tf32_kernel, cudaFuncAttributeMaxDynamicSharedMemorySize, SMEM_BYTES);

    const int N = in_sizes[1] / (HW * HW);   // 2048
    dim3 grid(CCOLS / CT, N);                // (8, 2048)
    bmm_tf32_kernel<<<grid, THREADS, SMEM_BYTES>>>(x, attn, Dm, alpha, out);
}